// round 11
// baseline (speedup 1.0000x reference)
#include <cuda_runtime.h>
#include <cuda_fp16.h>
#include <cstdint>

// Problem constants (fixed by dataset)
#define NB    16
#define INCC  32
#define INNX  65536
#define OUTCC 32
#define OUTNX 8192
#define MAXD  16
#define NF    512     // NB*INCC feature columns
#define OB    8       // output nodes per CTA (one per warp)

// 32 MB int8 feature table (row = 512 bytes) + per-row fp32 scales.
// feat[inn][j] = x[n,c,inn]*weight[c,inn], j = n*32+c; tab8 = rint(feat/scale).
__device__ uint4 g_tab8[(size_t)INNX * NF / 16];
__device__ float g_scale[INNX];

// ---- prep dynamic smem layout (words = uint32) ----
// s_feat: [32 chunks][65 inn-slots][9 words] (8 data words = 16 halves + 1 pad)
#define PQ_FEAT_WORDS  (32 * 65 * 9)          // 18720 words = 74880 B
#define PQ_RED_OFF     PQ_FEAT_WORDS          // 4*64 floats
#define PQ_SCALE_OFF   (PQ_FEAT_WORDS + 256)  // 64 floats
#define PQ_TOTAL_BYTES ((PQ_FEAT_WORDS + 256 + 64) * 4)

// ---- packed f32x2 helpers (sm_103a FFMA2) ----
__device__ __forceinline__ unsigned long long pk2(float lo, float hi) {
    unsigned long long r;
    asm("mov.b64 %0,{%1,%2};" : "=l"(r) : "f"(lo), "f"(hi));
    return r;
}
__device__ __forceinline__ void upk2(unsigned long long v, float& lo, float& hi) {
    asm("mov.b64 {%0,%1},%2;" : "=f"(lo), "=f"(hi) : "l"(v));
}
__device__ __forceinline__ unsigned long long ffma2(unsigned long long a,
                                                    unsigned long long b,
                                                    unsigned long long c) {
    unsigned long long d;
    asm("fma.rn.f32x2 %0,%1,%2,%3;" : "=l"(d) : "l"(a), "l"(b), "l"(c));
    return d;
}

// 16B global load bypassing L1 allocation
__device__ __forceinline__ uint4 ldg_nc_na128(const void* p) {
    uint4 v;
    asm volatile("ld.global.nc.L1::no_allocate.v4.u32 {%0,%1,%2,%3}, [%4];"
                 : "=r"(v.x), "=r"(v.y), "=r"(v.z), "=r"(v.w) : "l"(p));
    return v;
}

// ---------------------------------------------------------------------------
// Kernel 1: scale + transpose + per-row int8 quantization.
// One CTA owns 64 full table rows (inn0..inn0+64): computes feat in fp32,
// tracks per-row max, stages fp16 in conflict-free smem, then quantizes and
// writes 512B-coalesced int8 rows + row scales.
// Thread map (compute): inn_l = t&63, jq = t>>6 owns j in [jq*128, jq*128+128).
// ---------------------------------------------------------------------------
__global__ __launch_bounds__(256) void prep_kernel_q(const float* __restrict__ x,
                                                     const float* __restrict__ w) {
    extern __shared__ __align__(16) uint32_t sq[];
    float* s_red   = (float*)(sq + PQ_RED_OFF);    // [4][64]
    float* s_scale = (float*)(sq + PQ_SCALE_OFF);  // [64] reciprocal scales

    const unsigned t     = threadIdx.x;
    const unsigned inn_l = t & 63;
    const unsigned jq    = t >> 6;
    const unsigned inn0  = blockIdx.x << 6;
    const unsigned inn   = inn0 + inn_l;

    float amax = 0.f;
#pragma unroll 8
    for (unsigned p = 0; p < 64; p++) {            // j-pairs
        const unsigned j  = jq * 128 + 2 * p;
        const unsigned c0 = j & 31;
        const unsigned c1 = (j + 1) & 31;
        const float a = __ldcs(x + j * (unsigned)INNX + inn)
                        * __ldg(w + c0 * (unsigned)INNX + inn);
        const float b = __ldcs(x + (j + 1) * (unsigned)INNX + inn)
                        * __ldg(w + c1 * (unsigned)INNX + inn);
        amax = fmaxf(amax, fmaxf(fabsf(a), fabsf(b)));
        // chunk = j>>4 (16 halves per chunk), word k = (j&15)>>1
        const unsigned chunk = j >> 4;
        const unsigned k     = (j & 15) >> 1;
        __half2 h = __floats2half2_rn(a, b);
        sq[chunk * 585 + inn_l * 9 + k] = *(const uint32_t*)&h;  // stride 9: conflict-free
    }
    s_red[jq * 64 + inn_l] = amax;
    __syncthreads();

    if (t < 64) {
        float m = fmaxf(fmaxf(s_red[t], s_red[64 + t]),
                        fmaxf(s_red[128 + t], s_red[192 + t]));
        const float rsc = (m > 0.f) ? (127.0f / m) : 0.f;
        s_scale[t] = rsc;
        g_scale[inn0 + t] = (m > 0.f) ? (m / 127.0f) : 0.f;
    }
    __syncthreads();

    // Write phase: e -> (inn_l2 = e>>5, chunk = e&31). Per warp: chunk = lane,
    // inn fixed -> 512B-coalesced global writes; LDS stride 585 % 32 = 9 -> CF.
    for (unsigned e = t; e < 2048; e += 256) {
        const unsigned il    = e >> 5;
        const unsigned chunk = e & 31;
        const float    rsc   = s_scale[il];
        const uint32_t* src  = sq + chunk * 585 + il * 9;
        uint4 outw;
        uint32_t* ow = &outw.x;
#pragma unroll
        for (int m = 0; m < 4; m++) {
            __half2 h0 = *(const __half2*)&src[2 * m];
            __half2 h1 = *(const __half2*)&src[2 * m + 1];
            float2 f0 = __half22float2(h0);
            float2 f1 = __half22float2(h1);
            int q0 = __float2int_rn(f0.x * rsc);
            int q1 = __float2int_rn(f0.y * rsc);
            int q2 = __float2int_rn(f1.x * rsc);
            int q3 = __float2int_rn(f1.y * rsc);
            ow[m] = (q0 & 0xff) | ((q1 & 0xff) << 8) | ((q2 & 0xff) << 16)
                  | ((unsigned)q3 << 24);
        }
        g_tab8[(size_t)(inn0 + il) * 32 + chunk] = outw;
    }
}

// ---------------------------------------------------------------------------
// Kernel 2: FUSED warp-per-output-node int8 gather + fp32 pool + FFMA2 GEMM
// + staged transposed store. One LDG.128 per (d,lane); weight*rowscale folded
// into the shuffled coefficient. Lane covers j [16L, 16L+16).
// Pooled permuted layout: quad k of lane L -> sp4[k*32 + L];
// GEMM inverse for j = 32t+4c4: idx = (c4&3)*32 + 2t + (c4>>2).
// ---------------------------------------------------------------------------
__global__ __launch_bounds__(256, 5) void gather_kernel(
    const void*  __restrict__ Araw,
    const float* __restrict__ mask,
    const float* __restrict__ mw,
    const float* __restrict__ ctw,
    const float* __restrict__ ctb,
    const float* __restrict__ bias,
    float* __restrict__ out)
{
    __shared__ __align__(16) float s_pool[OB][NF];   // permuted pooled (16 KB)
    __shared__ float s_stage[NF][OB + 1];            // output staging (18 KB)
    __shared__ int   s_is64;

    const int tid  = threadIdx.x;
    const int w    = tid >> 5;
    const int lane = tid & 31;

    if (tid == 0) {
        const long long* a64 = (const long long*)Araw;
        int is64 = 1;
#pragma unroll
        for (int i = 0; i < 8; i++)
            if ((unsigned long long)a64[i] >= (unsigned long long)INNX) is64 = 0;
        s_is64 = is64;
    }
    __syncthreads();
    const int is64 = s_is64;

    const int o_base = blockIdx.x * OB;
    const int o      = o_base + w;

    // neighbor indices + (pool weight * row scale), distributed in lanes 0..15
    unsigned av = 0;
    float    wsv = 0.f;
    if (lane < MAXD) {
        av = is64 ? (unsigned)((const long long*)Araw)[(size_t)o * MAXD + lane]
                  : (unsigned)((const int*)Araw)[(size_t)o * MAXD + lane];
        const float wv = mw[o * MAXD + lane] * mask[o * MAXD + lane];
        wsv = wv * __ldg(g_scale + av);
    }

    // ---- gather + pool (fp32 acc): lane covers 16 int8 = one uint4 ----
    float acc[16];
#pragma unroll
    for (int i = 0; i < 16; i++) acc[i] = 0.f;

#pragma unroll
    for (int d = 0; d < MAXD; d++) {
        const unsigned idx = __shfl_sync(0xffffffffu, av, d);
        const float    wd  = __shfl_sync(0xffffffffu, wsv, d);
        uint4 u = ldg_nc_na128(g_tab8 + (size_t)idx * 32 + lane);
        const uint32_t* uw = &u.x;
#pragma unroll
        for (int wi = 0; wi < 4; wi++) {
            const int word = (int)uw[wi];
            acc[4 * wi + 0] += wd * (float)((int)(signed char)(word));
            acc[4 * wi + 1] += wd * (float)((int)(signed char)(word >> 8));
            acc[4 * wi + 2] += wd * (float)((int)(signed char)(word >> 16));
            acc[4 * wi + 3] += wd * (float)(word >> 24);
        }
    }

    // permuted pooled stores: 4 coalesced conflict-free STS.128
    float4* sp4 = (float4*)s_pool[w];
    sp4[lane]      = make_float4(acc[0],  acc[1],  acc[2],  acc[3]);
    sp4[32 + lane] = make_float4(acc[4],  acc[5],  acc[6],  acc[7]);
    sp4[64 + lane] = make_float4(acc[8],  acc[9],  acc[10], acc[11]);
    sp4[96 + lane] = make_float4(acc[12], acc[13], acc[14], acc[15]);
    __syncwarp();

    // ---- ct_weight row packed in f32x2 regs AFTER gather ----
    unsigned long long wp[16];
    {
        const float4* cw4 = (const float4*)(ctw + lane * INCC);
#pragma unroll
        for (int q = 0; q < 8; q++) {
            float4 v = __ldg(cw4 + q);
            wp[2 * q]     = pk2(v.x, v.y);
            wp[2 * q + 1] = pk2(v.z, v.w);
        }
    }
    const float cb = __ldg(ctb + lane);

    // ---- GEMM in FFMA2 ----
    const ulonglong2* spv = (const ulonglong2*)s_pool[w];
#pragma unroll
    for (int t = 0; t < NB; t++) {
        unsigned long long y2 = pk2(cb, 0.f);
#pragma unroll
        for (int c4 = 0; c4 < 8; c4++) {
            // inverse of permuted layout for j = t*32 + 4*c4
            const int idx = (c4 & 3) * 32 + 2 * t + (c4 >> 2);
            ulonglong2 pv = spv[idx];
            y2 = ffma2(pv.x, wp[2 * c4], y2);
            y2 = ffma2(pv.y, wp[2 * c4 + 1], y2);
        }
        float lo, hi; upk2(y2, lo, hi);
        s_stage[t * 32 + lane][w] = lo + hi;
    }
    __syncthreads();

    // ---- coalesced write-out: out[row*8192 + o] = stage + bias ----
#pragma unroll
    for (int e = tid; e < NF * OB; e += 256) {
        const int row  = e >> 3;
        const int col  = e & 7;
        const int oo   = o_base + col;
        const int dout = row & 31;
        out[(size_t)row * OUTNX + oo] = s_stage[row][col] + __ldg(bias + (size_t)dout * OUTNX + oo);
    }
}

extern "C" void kernel_launch(void* const* d_in, const int* in_sizes, int n_in,
                              void* d_out, int out_size) {
    const float* x    = (const float*)d_in[0];
    const void*  A    = d_in[1];
    const float* w    = (const float*)d_in[2];
    const float* mask = (const float*)d_in[3];
    const float* mw   = (const float*)d_in[4];
    const float* ctw  = (const float*)d_in[5];
    const float* ctb  = (const float*)d_in[6];
    const float* bias = (const float*)d_in[7];
    float* out = (float*)d_out;
    (void)in_sizes; (void)n_in; (void)out_size;

    cudaFuncSetAttribute(prep_kernel_q,
                         cudaFuncAttributeMaxDynamicSharedMemorySize, PQ_TOTAL_BYTES);

    prep_kernel_q<<<INNX / 64, 256, PQ_TOTAL_BYTES>>>(x, w);

    gather_kernel<<<OUTNX / OB, 256>>>(A, mask, mw, ctw, ctb, bias, out);
}

// round 12
// speedup vs baseline: 1.3592x; 1.3592x over previous
#include <cuda_runtime.h>
#include <cuda_fp16.h>
#include <cstdint>

// Problem constants (fixed by dataset)
#define NB    16
#define INCC  32
#define INNX  65536
#define OUTCC 32
#define OUTNX 8192
#define MAXD  16
#define NF    512     // NB*INCC feature columns
#define OB    8       // output nodes per CTA (one per warp)

// 64 MB fp16 feature table: feat[inn][j] = x[n,c,inn]*weight[c,inn], j = n*32+c
__device__ __half g_feat_h[(size_t)INNX * NF];

// ---- packed f32x2 helpers (sm_103a FFMA2) ----
__device__ __forceinline__ unsigned long long pk2(float lo, float hi) {
    unsigned long long r;
    asm("mov.b64 %0,{%1,%2};" : "=l"(r) : "f"(lo), "f"(hi));
    return r;
}
__device__ __forceinline__ void upk2(unsigned long long v, float& lo, float& hi) {
    asm("mov.b64 {%0,%1},%2;" : "=f"(lo), "=f"(hi) : "l"(v));
}
__device__ __forceinline__ unsigned long long ffma2(unsigned long long a,
                                                    unsigned long long b,
                                                    unsigned long long c) {
    unsigned long long d;
    asm("fma.rn.f32x2 %0,%1,%2,%3;" : "=l"(d) : "l"(a), "l"(b), "l"(c));
    return d;
}

// ---------------------------------------------------------------------------
// Kernel 1 (proven ~29us): fused scale + transpose + fp32->fp16.
// Tile = 64 j x 64 inn, MLP 16, 32-bit indexing, conflict-free half2 smem,
// 128B coalesced half2 row stores; __ldcs on x.
// ---------------------------------------------------------------------------
__global__ __launch_bounds__(256) void prep_kernel(const float* __restrict__ x,
                                                   const float* __restrict__ w) {
    __shared__ __half2 t2[32][65];
    const unsigned inn0 = blockIdx.x << 6;
    const unsigned j0   = blockIdx.y << 6;
    const unsigned tx = threadIdx.x, ty = threadIdx.y;   // 32 x 8

#pragma unroll
    for (int k = 0; k < 4; k++) {
        const unsigned jh = ty + (k << 3);
        const unsigned j  = j0 + 2 * jh;
        const unsigned c0 = j & 31;
        const unsigned c1 = (j + 1) & 31;
        const unsigned bx0 = j * INNX + inn0 + tx;
        const unsigned bw0 = c0 * INNX + inn0 + tx;
        const unsigned bw1 = c1 * INNX + inn0 + tx;
        const float a0 = __ldcs(x + bx0)              * __ldg(w + bw0);
        const float b0 = __ldcs(x + bx0 + INNX)       * __ldg(w + bw1);
        const float a1 = __ldcs(x + bx0 + 32)         * __ldg(w + bw0 + 32);
        const float b1 = __ldcs(x + bx0 + INNX + 32)  * __ldg(w + bw1 + 32);
        t2[jh][tx]      = __floats2half2_rn(a0, b0);
        t2[jh][tx + 32] = __floats2half2_rn(a1, b1);
    }
    __syncthreads();

    __half2* out2 = (__half2*)g_feat_h;   // row stride = 256 half2
    const unsigned tid = (ty << 5) + tx;
#pragma unroll
    for (int k = 0; k < 8; k++) {
        const unsigned e     = tid + (k << 8);
        const unsigned inn_l = e >> 5;
        const unsigned jh    = e & 31;
        out2[(inn0 + inn_l) * 256u + (j0 >> 1) + jh] = t2[jh][inn_l];
    }
}

// ---------------------------------------------------------------------------
// Kernel 2: FUSED warp-per-output-node gather + HFMA2 pool + FFMA2 GEMM +
// staged transposed store. Gather loop is software-pipelined (prefetch d+1's
// two LDG.128 while consuming d) to double in-flight memory; 5 CTAs/SM.
// ---------------------------------------------------------------------------
__global__ __launch_bounds__(256, 5) void gather_kernel(
    const void*  __restrict__ Araw,
    const float* __restrict__ mask,
    const float* __restrict__ mw,
    const float* __restrict__ ctw,
    const float* __restrict__ ctb,
    const float* __restrict__ bias,
    float* __restrict__ out)
{
    __shared__ __align__(16) float s_pool[OB][NF];   // permuted pooled (16 KB)
    __shared__ float s_stage[NF][OB + 1];            // output staging (18 KB)
    __shared__ int   s_is64;

    const int tid  = threadIdx.x;
    const int w    = tid >> 5;
    const int lane = tid & 31;

    if (tid == 0) {
        const long long* a64 = (const long long*)Araw;
        int is64 = 1;
#pragma unroll
        for (int i = 0; i < 8; i++)
            if ((unsigned long long)a64[i] >= (unsigned long long)INNX) is64 = 0;
        s_is64 = is64;
    }
    __syncthreads();
    const int is64 = s_is64;

    const int o_base = blockIdx.x * OB;
    const int o      = o_base + w;

    // neighbor indices + pooling weights, distributed in lanes 0..15
    unsigned av = 0;
    float    wv = 0.f;
    if (lane < MAXD) {
        av = is64 ? (unsigned)((const long long*)Araw)[(size_t)o * MAXD + lane]
                  : (unsigned)((const int*)Araw)[(size_t)o * MAXD + lane];
        wv = mw[o * MAXD + lane] * mask[o * MAXD + lane];
    }

    // ---- gather + pool in half2 (HFMA2), software-pipelined ----
    const uint4* feat4 = (const uint4*)g_feat_h;   // row stride = 64 uint4
    __half2 acc[8];
#pragma unroll
    for (int i = 0; i < 8; i++) acc[i] = __float2half2_rn(0.f);

    uint4 u0, u1;
    {
        const unsigned idx0 = __shfl_sync(0xffffffffu, av, 0);
        const uint4* row = feat4 + (size_t)idx0 * 64;
        u0 = __ldg(row + lane);
        u1 = __ldg(row + lane + 32);
    }
#pragma unroll
    for (int d = 0; d < MAXD; d++) {
        uint4 n0, n1;
        if (d + 1 < MAXD) {
            const unsigned idxn = __shfl_sync(0xffffffffu, av, d + 1);
            const uint4* row = feat4 + (size_t)idxn * 64;
            n0 = __ldg(row + lane);
            n1 = __ldg(row + lane + 32);
        }
        const float   wd = __shfl_sync(0xffffffffu, wv, d);
        const __half2 wh = __half2half2(__float2half_rn(wd));
        const __half2* h0 = (const __half2*)&u0;
        const __half2* h1 = (const __half2*)&u1;
#pragma unroll
        for (int q = 0; q < 4; q++) {
            acc[q]     = __hfma2(h0[q], wh, acc[q]);
            acc[4 + q] = __hfma2(h1[q], wh, acc[4 + q]);
        }
        if (d + 1 < MAXD) { u0 = n0; u1 = n1; }
    }

    // permuted pooled stores: 4 coalesced conflict-free STS.128
    float4* sp4 = (float4*)s_pool[w];
    {
        float2 f0 = __half22float2(acc[0]), f1 = __half22float2(acc[1]);
        float2 f2 = __half22float2(acc[2]), f3 = __half22float2(acc[3]);
        float2 f4 = __half22float2(acc[4]), f5 = __half22float2(acc[5]);
        float2 f6 = __half22float2(acc[6]), f7 = __half22float2(acc[7]);
        sp4[lane]      = make_float4(f0.x, f0.y, f1.x, f1.y);
        sp4[32 + lane] = make_float4(f2.x, f2.y, f3.x, f3.y);
        sp4[64 + lane] = make_float4(f4.x, f4.y, f5.x, f5.y);
        sp4[96 + lane] = make_float4(f6.x, f6.y, f7.x, f7.y);
    }
    __syncwarp();

    // ---- ct_weight row packed in f32x2 regs AFTER gather ----
    unsigned long long wp[16];
    {
        const float4* cw4 = (const float4*)(ctw + lane * INCC);
#pragma unroll
        for (int q = 0; q < 8; q++) {
            float4 v = __ldg(cw4 + q);
            wp[2 * q]     = pk2(v.x, v.y);
            wp[2 * q + 1] = pk2(v.z, v.w);
        }
    }
    const float cb = __ldg(ctb + lane);

    // ---- GEMM in FFMA2 ----
    const ulonglong2* spv = (const ulonglong2*)s_pool[w];
#pragma unroll
    for (int t = 0; t < NB; t++) {
        unsigned long long y2 = pk2(cb, 0.f);
#pragma unroll
        for (int c4 = 0; c4 < 8; c4++) {
            // inverse of permuted layout for j = t*32 + 4*c4
            const int idx = ((t >> 3) ? 64 : 0) + ((c4 & 1) ? 32 : 0)
                          + 4 * (t & 7) + (c4 >> 1);
            ulonglong2 pv = spv[idx];
            y2 = ffma2(pv.x, wp[2 * c4], y2);
            y2 = ffma2(pv.y, wp[2 * c4 + 1], y2);
        }
        float lo, hi; upk2(y2, lo, hi);
        s_stage[t * 32 + lane][w] = lo + hi;
    }
    __syncthreads();

    // ---- coalesced write-out: out[row*8192 + o] = stage + bias ----
#pragma unroll
    for (int e = tid; e < NF * OB; e += 256) {
        const int row  = e >> 3;
        const int col  = e & 7;
        const int oo   = o_base + col;
        const int dout = row & 31;
        out[(size_t)row * OUTNX + oo] = s_stage[row][col] + __ldg(bias + (size_t)dout * OUTNX + oo);
    }
}

extern "C" void kernel_launch(void* const* d_in, const int* in_sizes, int n_in,
                              void* d_out, int out_size) {
    const float* x    = (const float*)d_in[0];
    const void*  A    = d_in[1];
    const float* w    = (const float*)d_in[2];
    const float* mask = (const float*)d_in[3];
    const float* mw   = (const float*)d_in[4];
    const float* ctw  = (const float*)d_in[5];
    const float* ctb  = (const float*)d_in[6];
    const float* bias = (const float*)d_in[7];
    float* out = (float*)d_out;
    (void)in_sizes; (void)n_in; (void)out_size;

    dim3 pgrid(INNX / 64, NF / 64);
    dim3 pblk(32, 8);
    prep_kernel<<<pgrid, pblk>>>(x, w);

    gather_kernel<<<OUTNX / OB, 256>>>(A, mask, mw, ctw, ctb, bias, out);
}

// round 14
// speedup vs baseline: 1.4802x; 1.0890x over previous
#include <cuda_runtime.h>
#include <cuda_fp16.h>
#include <cstdint>

// Problem constants (fixed by dataset)
#define NB    16
#define INCC  32
#define INNX  65536
#define OUTCC 32
#define OUTNX 8192
#define MAXD  16
#define NF    512     // NB*INCC feature columns
#define OB    8       // output nodes per CTA (one per warp)

// 32 MB int8 feature table (row = 512 B) + per-row fp32 scales.
__device__ uint4 g_tab8[(size_t)INNX * 32];
__device__ float g_scale[INNX];

// ---- prep_q3 smem layout (uint32 words) ----
// staging: [32 inn][260] half2 words (256 data + 4 pad); stride 260 words
// = 1040 B == 0 mod 16 -> every row base is 16B-aligned for LDS.128.
#define P3_STRIDE      260
#define P3_STAGE_WORDS (32 * P3_STRIDE)            // 8320 words
#define P3_RED_OFF     P3_STAGE_WORDS              // 8*32 floats
#define P3_SCALE_OFF   (P3_STAGE_WORDS + 256)      // 32 floats
#define P3_TOTAL_BYTES ((P3_STAGE_WORDS + 256 + 32) * 4)

// ---- packed f32x2 helpers (sm_103a FFMA2) ----
__device__ __forceinline__ unsigned long long pk2(float lo, float hi) {
    unsigned long long r;
    asm("mov.b64 %0,{%1,%2};" : "=l"(r) : "f"(lo), "f"(hi));
    return r;
}
__device__ __forceinline__ void upk2(unsigned long long v, float& lo, float& hi) {
    asm("mov.b64 {%0,%1},%2;" : "=f"(lo), "=f"(hi) : "l"(v));
}
__device__ __forceinline__ unsigned long long ffma2(unsigned long long a,
                                                    unsigned long long b,
                                                    unsigned long long c) {
    unsigned long long d;
    asm("fma.rn.f32x2 %0,%1,%2,%3;" : "=l"(d) : "l"(a), "l"(b), "l"(c));
    return d;
}

// 16B global load bypassing L1 allocation
__device__ __forceinline__ uint4 ldg_nc_na128(const void* p) {
    uint4 v;
    asm volatile("ld.global.nc.L1::no_allocate.v4.u32 {%0,%1,%2,%3}, [%4];"
                 : "=r"(v.x), "=r"(v.y), "=r"(v.z), "=r"(v.w) : "l"(p));
    return v;
}

// ---------------------------------------------------------------------------
// Kernel 1: scale + transpose + per-ROW int8 quantization, high occupancy.
// One CTA owns 32 complete table rows. 256 thr = 32 tx x 8 ty.
// Phase 1: thread (tx,ty) computes 32 j-pairs (jh = ty+8p), tracks |max|,
//          stages half2 at sq[tx*260 + jh].
// Phase 2: per-row max over ty -> scale.
// Phase 3: lane L loads 2 x uint4 (16 halves, j = 16L..16L+16) -- aligned --
//          quantizes, writes one uint4 -> 512B-contiguous per warp.
// ---------------------------------------------------------------------------
__global__ __launch_bounds__(256) void prep_q3(const float* __restrict__ x,
                                               const float* __restrict__ w) {
    extern __shared__ __align__(16) uint32_t sq[];
    float* s_red   = (float*)(sq + P3_RED_OFF);    // [8][32]
    float* s_scale = (float*)(sq + P3_SCALE_OFF);  // [32] reciprocal scales

    const unsigned tid = threadIdx.x;
    const unsigned tx  = tid & 31;
    const unsigned ty  = tid >> 5;
    const unsigned inn0 = blockIdx.x << 5;
    const unsigned inn  = inn0 + tx;

    float amax = 0.f;
#pragma unroll 4
    for (unsigned p = 0; p < 32; p++) {
        const unsigned jh = ty + (p << 3);          // 0..255 (half2 index)
        const unsigned j  = 2 * jh;
        const unsigned c0 = j & 31;
        const unsigned c1 = (j + 1) & 31;
        const float a = __ldcs(x + j * (unsigned)INNX + inn)
                        * __ldg(w + c0 * (unsigned)INNX + inn);
        const float b = __ldcs(x + (j + 1) * (unsigned)INNX + inn)
                        * __ldg(w + c1 * (unsigned)INNX + inn);
        amax = fmaxf(amax, fmaxf(fabsf(a), fabsf(b)));
        __half2 h = __floats2half2_rn(a, b);
        sq[tx * P3_STRIDE + jh] = *(const uint32_t*)&h;
    }
    s_red[ty * 32 + tx] = amax;
    __syncthreads();

    if (tid < 32) {
        float m = s_red[tid];
#pragma unroll
        for (int r = 1; r < 8; r++) m = fmaxf(m, s_red[r * 32 + tid]);
        s_scale[tid] = (m > 0.f) ? (127.0f / m) : 0.f;
        g_scale[inn0 + tid] = (m > 0.f) ? (m / 127.0f) : 0.f;
    }
    __syncthreads();

    // Phase 3: 4 iterations; warp handles one inn row per iter.
    const unsigned L = tid & 31;
#pragma unroll
    for (int iter = 0; iter < 4; iter++) {
        const unsigned il = (tid >> 5) + (iter << 3);   // 0..31
        const float rsc = s_scale[il];
        const uint32_t* rb = sq + il * P3_STRIDE + L * 8;
        uint4 hv0 = *(const uint4*)(rb);       // 8 halves (j = 16L..16L+8)
        uint4 hv1 = *(const uint4*)(rb + 4);   // 8 halves (j = 16L+8..16L+16)
        __half2 h2[8];
        *(uint4*)&h2[0] = hv0;
        *(uint4*)&h2[4] = hv1;
        uint4 outw;
        uint32_t* ow = &outw.x;
#pragma unroll
        for (int m = 0; m < 4; m++) {
            float2 f0 = __half22float2(h2[2 * m]);
            float2 f1 = __half22float2(h2[2 * m + 1]);
            int q0 = __float2int_rn(f0.x * rsc);
            int q1 = __float2int_rn(f0.y * rsc);
            int q2 = __float2int_rn(f1.x * rsc);
            int q3 = __float2int_rn(f1.y * rsc);
            ow[m] = (q0 & 0xff) | ((q1 & 0xff) << 8) | ((q2 & 0xff) << 16)
                  | ((unsigned)q3 << 24);
        }
        g_tab8[(size_t)(inn0 + il) * 32 + L] = outw;
    }
}

// ---------------------------------------------------------------------------
// Kernel 2 (R11 gather VERBATIM, measured 30.4us): warp-per-output-node int8
// gather + fp32 pool + FFMA2 GEMM + staged transposed store.
// ---------------------------------------------------------------------------
__global__ __launch_bounds__(256, 5) void gather_kernel(
    const void*  __restrict__ Araw,
    const float* __restrict__ mask,
    const float* __restrict__ mw,
    const float* __restrict__ ctw,
    const float* __restrict__ ctb,
    const float* __restrict__ bias,
    float* __restrict__ out)
{
    __shared__ __align__(16) float s_pool[OB][NF];   // permuted pooled (16 KB)
    __shared__ float s_stage[NF][OB + 1];            // output staging (18 KB)
    __shared__ int   s_is64;

    const int tid  = threadIdx.x;
    const int w    = tid >> 5;
    const int lane = tid & 31;

    if (tid == 0) {
        const long long* a64 = (const long long*)Araw;
        int is64 = 1;
#pragma unroll
        for (int i = 0; i < 8; i++)
            if ((unsigned long long)a64[i] >= (unsigned long long)INNX) is64 = 0;
        s_is64 = is64;
    }
    __syncthreads();
    const int is64 = s_is64;

    const int o_base = blockIdx.x * OB;
    const int o      = o_base + w;

    unsigned av = 0;
    float    wsv = 0.f;
    if (lane < MAXD) {
        av = is64 ? (unsigned)((const long long*)Araw)[(size_t)o * MAXD + lane]
                  : (unsigned)((const int*)Araw)[(size_t)o * MAXD + lane];
        const float wv = mw[o * MAXD + lane] * mask[o * MAXD + lane];
        wsv = wv * __ldg(g_scale + av);
    }

    float acc[16];
#pragma unroll
    for (int i = 0; i < 16; i++) acc[i] = 0.f;

#pragma unroll
    for (int d = 0; d < MAXD; d++) {
        const unsigned idx = __shfl_sync(0xffffffffu, av, d);
        const float    wd  = __shfl_sync(0xffffffffu, wsv, d);
        uint4 u = ldg_nc_na128(g_tab8 + (size_t)idx * 32 + lane);
        const uint32_t* uw = &u.x;
#pragma unroll
        for (int wi = 0; wi < 4; wi++) {
            const int word = (int)uw[wi];
            acc[4 * wi + 0] += wd * (float)((int)(signed char)(word));
            acc[4 * wi + 1] += wd * (float)((int)(signed char)(word >> 8));
            acc[4 * wi + 2] += wd * (float)((int)(signed char)(word >> 16));
            acc[4 * wi + 3] += wd * (float)(word >> 24);
        }
    }

    float4* sp4 = (float4*)s_pool[w];
    sp4[lane]      = make_float4(acc[0],  acc[1],  acc[2],  acc[3]);
    sp4[32 + lane] = make_float4(acc[4],  acc[5],  acc[6],  acc[7]);
    sp4[64 + lane] = make_float4(acc[8],  acc[9],  acc[10], acc[11]);
    sp4[96 + lane] = make_float4(acc[12], acc[13], acc[14], acc[15]);
    __syncwarp();

    unsigned long long wp[16];
    {
        const float4* cw4 = (const float4*)(ctw + lane * INCC);
#pragma unroll
        for (int q = 0; q < 8; q++) {
            float4 v = __ldg(cw4 + q);
            wp[2 * q]     = pk2(v.x, v.y);
            wp[2 * q + 1] = pk2(v.z, v.w);
        }
    }
    const float cb = __ldg(ctb + lane);

    const ulonglong2* spv = (const ulonglong2*)s_pool[w];
#pragma unroll
    for (int t = 0; t < NB; t++) {
        unsigned long long y2 = pk2(cb, 0.f);
#pragma unroll
        for (int c4 = 0; c4 < 8; c4++) {
            const int idx = (c4 & 3) * 32 + 2 * t + (c4 >> 2);
            ulonglong2 pv = spv[idx];
            y2 = ffma2(pv.x, wp[2 * c4], y2);
            y2 = ffma2(pv.y, wp[2 * c4 + 1], y2);
        }
        float lo, hi; upk2(y2, lo, hi);
        s_stage[t * 32 + lane][w] = lo + hi;
    }
    __syncthreads();

#pragma unroll
    for (int e = tid; e < NF * OB; e += 256) {
        const int row  = e >> 3;
        const int col  = e & 7;
        const int oo   = o_base + col;
        const int dout = row & 31;
        out[(size_t)row * OUTNX + oo] = s_stage[row][col] + __ldg(bias + (size_t)dout * OUTNX + oo);
    }
}

extern "C" void kernel_launch(void* const* d_in, const int* in_sizes, int n_in,
                              void* d_out, int out_size) {
    const float* x    = (const float*)d_in[0];
    const void*  A    = d_in[1];
    const float* w    = (const float*)d_in[2];
    const float* mask = (const float*)d_in[3];
    const float* mw   = (const float*)d_in[4];
    const float* ctw  = (const float*)d_in[5];
    const float* ctb  = (const float*)d_in[6];
    const float* bias = (const float*)d_in[7];
    float* out = (float*)d_out;
    (void)in_sizes; (void)n_in; (void)out_size;

    prep_q3<<<INNX / 32, 256, P3_TOTAL_BYTES>>>(x, w);

    gather_kernel<<<OUTNX / OB, 256>>>(A, mask, mw, ctw, ctb, bias, out);
}

// round 15
// speedup vs baseline: 1.5221x; 1.0283x over previous
#include <cuda_runtime.h>
#include <cuda_fp16.h>
#include <cstdint>

// Problem constants (fixed by dataset)
#define NB    16
#define INCC  32
#define INNX  65536
#define OUTCC 32
#define OUTNX 8192
#define MAXD  16
#define NF    512     // NB*INCC feature columns
#define OB    8       // output nodes per CTA (one per warp)

// 32 MB biased-u8 feature table (row = 512 B, byte = q+128) + per-row scales.
__device__ uint4 g_tab8[(size_t)INNX * 32];
__device__ float g_scale[INNX];

// ---- prep_q4 smem layout ----
// staging: uint4 sq4[32 rows][65] (64 data groups of 8 j + 1 pad uint4)
// odd uint4 stride -> conflict-free STS.128 (bank-group = (65r+g)%8, distinct
// within each 8-lane phase); 16B alignment guaranteed by construction.
#define P4_STAGE_U4   (32 * 65)                  // 2080 uint4 = 33280 B
#define P4_RED_OFF    (P4_STAGE_U4 * 4)          // word offset: 8*32 floats
#define P4_SCALE_OFF  (P4_STAGE_U4 * 4 + 256)    // 32 floats
#define P4_TOTAL_BYTES ((P4_STAGE_U4 * 4 + 256 + 32) * 4)

// ---- packed f32x2 helpers (sm_103a FFMA2) ----
__device__ __forceinline__ unsigned long long pk2(float lo, float hi) {
    unsigned long long r;
    asm("mov.b64 %0,{%1,%2};" : "=l"(r) : "f"(lo), "f"(hi));
    return r;
}
__device__ __forceinline__ void upk2(unsigned long long v, float& lo, float& hi) {
    asm("mov.b64 {%0,%1},%2;" : "=f"(lo), "=f"(hi) : "l"(v));
}
__device__ __forceinline__ unsigned long long ffma2(unsigned long long a,
                                                    unsigned long long b,
                                                    unsigned long long c) {
    unsigned long long d;
    asm("fma.rn.f32x2 %0,%1,%2,%3;" : "=l"(d) : "l"(a), "l"(b), "l"(c));
    return d;
}

// 16B global load bypassing L1 allocation
__device__ __forceinline__ uint4 ldg_nc_na128(const void* p) {
    uint4 v;
    asm volatile("ld.global.nc.L1::no_allocate.v4.u32 {%0,%1,%2,%3}, [%4];"
                 : "=r"(v.x), "=r"(v.y), "=r"(v.z), "=r"(v.w) : "l"(p));
    return v;
}

// ---------------------------------------------------------------------------
// Kernel 1: scale + transpose + per-ROW biased-u8 quantization.
// One CTA owns 32 complete table rows. Thread (L=lane, wy=warp):
// Phase 1: 8 groups g = wy+8i; per group 8 coalesced x loads (j=8g..8g+8,
//          inn = inn0+L), track |max|, pack 4 half2, STS.128 (conflict-free).
// Phase 2: per-row max over 8 warps -> scale.
// Phase 3: warp handles row r = wy+8*iter; lane L loads 2 uint4 (j=16L..16L+16,
//          2-way LDS), quantizes to u8 = round(f*rsc)+128, one coalesced
//          STG.128 per lane -> 512B-contiguous row segment.
// ---------------------------------------------------------------------------
__global__ __launch_bounds__(256) void prep_q4(const float* __restrict__ x,
                                               const float* __restrict__ w) {
    extern __shared__ __align__(16) uint32_t sqw[];
    uint4* sq4     = (uint4*)sqw;
    float* s_red   = (float*)(sqw + P4_RED_OFF);    // [8][32]
    float* s_scale = (float*)(sqw + P4_SCALE_OFF);  // [32] reciprocal scales

    const unsigned tid = threadIdx.x;
    const unsigned L   = tid & 31;
    const unsigned wy  = tid >> 5;
    const unsigned inn0 = blockIdx.x << 5;
    const unsigned inn  = inn0 + L;

    float amax = 0.f;
#pragma unroll
    for (unsigned i = 0; i < 8; i++) {
        const unsigned g  = wy + (i << 3);       // uint4 group 0..63
        const unsigned j0 = g << 3;              // 8 j-values per group
        float v[8];
#pragma unroll
        for (unsigned k = 0; k < 8; k++) {
            const unsigned j = j0 + k;
            v[k] = __ldcs(x + j * (unsigned)INNX + inn)
                   * __ldg(w + (j & 31) * (unsigned)INNX + inn);
            amax = fmaxf(amax, fabsf(v[k]));
        }
        uint4 pk4;
        __half2 h0 = __floats2half2_rn(v[0], v[1]);
        __half2 h1 = __floats2half2_rn(v[2], v[3]);
        __half2 h2 = __floats2half2_rn(v[4], v[5]);
        __half2 h3 = __floats2half2_rn(v[6], v[7]);
        pk4.x = *(const uint32_t*)&h0;
        pk4.y = *(const uint32_t*)&h1;
        pk4.z = *(const uint32_t*)&h2;
        pk4.w = *(const uint32_t*)&h3;
        sq4[L * 65 + g] = pk4;                   // conflict-free STS.128
    }
    s_red[wy * 32 + L] = amax;
    __syncthreads();

    if (tid < 32) {
        float m = s_red[tid];
#pragma unroll
        for (int r = 1; r < 8; r++) m = fmaxf(m, s_red[r * 32 + tid]);
        s_scale[tid] = (m > 0.f) ? (127.0f / m) : 0.f;
        g_scale[inn0 + tid] = (m > 0.f) ? (m / 127.0f) : 0.f;
    }
    __syncthreads();

#pragma unroll
    for (int iter = 0; iter < 4; iter++) {
        const unsigned r = wy + (iter << 3);     // row 0..31
        const float rsc = s_scale[r];
        uint4 a = sq4[r * 65 + 2 * L];           // j = 16L..16L+8
        uint4 b = sq4[r * 65 + 2 * L + 1];       // j = 16L+8..16L+16
        __half2 h2v[8];
        *(uint4*)&h2v[0] = a;
        *(uint4*)&h2v[4] = b;
        uint4 outw;
        uint32_t* ow = &outw.x;
#pragma unroll
        for (int m = 0; m < 4; m++) {
            float2 f0 = __half22float2(h2v[2 * m]);
            float2 f1 = __half22float2(h2v[2 * m + 1]);
            int q0 = __float2int_rn(fmaf(f0.x, rsc, 128.f));
            int q1 = __float2int_rn(fmaf(f0.y, rsc, 128.f));
            int q2 = __float2int_rn(fmaf(f1.x, rsc, 128.f));
            int q3 = __float2int_rn(fmaf(f1.y, rsc, 128.f));
            ow[m] = (unsigned)q0 | ((unsigned)q1 << 8) | ((unsigned)q2 << 16)
                  | ((unsigned)q3 << 24);
        }
        g_tab8[(size_t)(inn0 + r) * 32 + L] = outw;
    }
}

// ---------------------------------------------------------------------------
// Kernel 2: warp-per-output-node biased-u8 gather + PRMT/HFMA2 pool + FFMA2
// GEMM + staged transposed store. Unpack: byte b -> half(1024+b) via PRMT
// with 0x64 magic, HSUB2(1152) recovers exact q, HFMA2 accumulates.
// ---------------------------------------------------------------------------
__global__ __launch_bounds__(256, 5) void gather_kernel(
    const void*  __restrict__ Araw,
    const float* __restrict__ mask,
    const float* __restrict__ mw,
    const float* __restrict__ ctw,
    const float* __restrict__ ctb,
    const float* __restrict__ bias,
    float* __restrict__ out)
{
    __shared__ __align__(16) float s_pool[OB][NF];   // permuted pooled (16 KB)
    __shared__ float s_stage[NF][OB + 1];            // output staging (18 KB)
    __shared__ int   s_is64;

    const int tid  = threadIdx.x;
    const int w    = tid >> 5;
    const int lane = tid & 31;

    if (tid == 0) {
        const long long* a64 = (const long long*)Araw;
        int is64 = 1;
#pragma unroll
        for (int i = 0; i < 8; i++)
            if ((unsigned long long)a64[i] >= (unsigned long long)INNX) is64 = 0;
        s_is64 = is64;
    }
    __syncthreads();
    const int is64 = s_is64;

    const int o_base = blockIdx.x * OB;
    const int o      = o_base + w;

    unsigned av = 0;
    float    wsv = 0.f;
    if (lane < MAXD) {
        av = is64 ? (unsigned)((const long long*)Araw)[(size_t)o * MAXD + lane]
                  : (unsigned)((const int*)Araw)[(size_t)o * MAXD + lane];
        const float wv = mw[o * MAXD + lane] * mask[o * MAXD + lane];
        wsv = wv * __ldg(g_scale + av);
    }

    // half2 accumulators: acc[2wi] = j pair (4wi,4wi+1), acc[2wi+1] = (+2,+3)
    const __half2 c1152 = __floats2half2_rn(1152.f, 1152.f);
    __half2 acc[8];
#pragma unroll
    for (int i = 0; i < 8; i++) acc[i] = __float2half2_rn(0.f);

#pragma unroll
    for (int d = 0; d < MAXD; d++) {
        const unsigned idx = __shfl_sync(0xffffffffu, av, d);
        const float    wd  = __shfl_sync(0xffffffffu, wsv, d);
        const __half2  wh  = __half2half2(__float2half_rn(wd));
        uint4 u = ldg_nc_na128(g_tab8 + (size_t)idx * 32 + lane);
        const uint32_t* uw = &u.x;
#pragma unroll
        for (int wi = 0; wi < 4; wi++) {
            const uint32_t word = uw[wi];
            uint32_t lo = __byte_perm(word, 0x64646464u, 0x4140);
            uint32_t hi = __byte_perm(word, 0x64646464u, 0x4342);
            __half2 hlo = __hsub2(*(const __half2*)&lo, c1152);  // exact q pair
            __half2 hhi = __hsub2(*(const __half2*)&hi, c1152);
            acc[2 * wi]     = __hfma2(hlo, wh, acc[2 * wi]);
            acc[2 * wi + 1] = __hfma2(hhi, wh, acc[2 * wi + 1]);
        }
    }

    // permuted pooled stores: 4 coalesced conflict-free STS.128
    float4* sp4 = (float4*)s_pool[w];
    {
        float2 f0 = __half22float2(acc[0]), f1 = __half22float2(acc[1]);
        float2 f2 = __half22float2(acc[2]), f3 = __half22float2(acc[3]);
        float2 f4 = __half22float2(acc[4]), f5 = __half22float2(acc[5]);
        float2 f6 = __half22float2(acc[6]), f7 = __half22float2(acc[7]);
        sp4[lane]      = make_float4(f0.x, f0.y, f1.x, f1.y);
        sp4[32 + lane] = make_float4(f2.x, f2.y, f3.x, f3.y);
        sp4[64 + lane] = make_float4(f4.x, f4.y, f5.x, f5.y);
        sp4[96 + lane] = make_float4(f6.x, f6.y, f7.x, f7.y);
    }
    __syncwarp();

    unsigned long long wp[16];
    {
        const float4* cw4 = (const float4*)(ctw + lane * INCC);
#pragma unroll
        for (int q = 0; q < 8; q++) {
            float4 v = __ldg(cw4 + q);
            wp[2 * q]     = pk2(v.x, v.y);
            wp[2 * q + 1] = pk2(v.z, v.w);
        }
    }
    const float cb = __ldg(ctb + lane);

    const ulonglong2* spv = (const ulonglong2*)s_pool[w];
#pragma unroll
    for (int t = 0; t < NB; t++) {
        unsigned long long y2 = pk2(cb, 0.f);
#pragma unroll
        for (int c4 = 0; c4 < 8; c4++) {
            const int idx = (c4 & 3) * 32 + 2 * t + (c4 >> 2);
            ulonglong2 pv = spv[idx];
            y2 = ffma2(pv.x, wp[2 * c4], y2);
            y2 = ffma2(pv.y, wp[2 * c4 + 1], y2);
        }
        float lo, hi; upk2(y2, lo, hi);
        s_stage[t * 32 + lane][w] = lo + hi;
    }
    __syncthreads();

#pragma unroll
    for (int e = tid; e < NF * OB; e += 256) {
        const int row  = e >> 3;
        const int col  = e & 7;
        const int oo   = o_base + col;
        const int dout = row & 31;
        out[(size_t)row * OUTNX + oo] = s_stage[row][col] + __ldg(bias + (size_t)dout * OUTNX + oo);
    }
}

extern "C" void kernel_launch(void* const* d_in, const int* in_sizes, int n_in,
                              void* d_out, int out_size) {
    const float* x    = (const float*)d_in[0];
    const void*  A    = d_in[1];
    const float* w    = (const float*)d_in[2];
    const float* mask = (const float*)d_in[3];
    const float* mw   = (const float*)d_in[4];
    const float* ctw  = (const float*)d_in[5];
    const float* ctb  = (const float*)d_in[6];
    const float* bias = (const float*)d_in[7];
    float* out = (float*)d_out;
    (void)in_sizes; (void)n_in; (void)out_size;

    prep_q4<<<INNX / 32, 256, P4_TOTAL_BYTES>>>(x, w);

    gather_kernel<<<OUTNX / OB, 256>>>(A, mask, mw, ctw, ctb, bias, out);
}